// round 3
// baseline (speedup 1.0000x reference)
#include <cuda_runtime.h>
#include <math.h>

#define L 512
#define DO 64      // D_ORIG
#define NH 8
#define DH 32
#define DE 256
#define SCALE 0.17677669529663687f  // 1/sqrt(32)

// Scratch (device globals — no allocations allowed)
__device__ float g_q[L*DE];
__device__ float g_k[L*DE];
__device__ float g_v[L*DE];
__device__ float g_p[L*512];            // [i][n*64+c], SCALE folded in
__device__ float g_sc[(size_t)L*L*NH];  // [i][j][n] base qk logits (SCALE folded)

// ---------------------------------------------------------------------------
// Kernel 1: q,k,v = x@W and p[i][n][c] = scale * sum_d We[c][n*32+d]*q[i][n*32+d]
// ---------------------------------------------------------------------------
__global__ void proj_kernel(const float* __restrict__ x, const float* __restrict__ Wq,
                            const float* __restrict__ Wk, const float* __restrict__ Wv,
                            const float* __restrict__ We) {
    int i = blockIdx.x, t = threadIdx.x;
    __shared__ float xs[DO];
    __shared__ float qs[DE];
    if (t < DO) xs[t] = x[i*DO + t];
    __syncthreads();
    float aq = 0.f, ak = 0.f, av = 0.f;
    #pragma unroll
    for (int d = 0; d < DO; d++) {
        float xv = xs[d];
        aq = fmaf(xv, Wq[d*DE + t], aq);
        ak = fmaf(xv, Wk[d*DE + t], ak);
        av = fmaf(xv, Wv[d*DE + t], av);
    }
    g_q[i*DE + t] = aq; g_k[i*DE + t] = ak; g_v[i*DE + t] = av;
    qs[t] = aq;
    __syncthreads();
    #pragma unroll
    for (int r = t; r < 512; r += 256) {
        int n = r >> 6, c = r & 63;
        float acc = 0.f;
        const float* wrow = &We[c*DE + n*DH];
        const float* qh   = &qs[n*DH];
        #pragma unroll
        for (int d = 0; d < DH; d++) acc = fmaf(wrow[d], qh[d], acc);
        g_p[i*512 + r] = acc * SCALE;
    }
}

// ---------------------------------------------------------------------------
// Kernel 2: base[i][j][n] = scale * q[i,nslice] . k[j,nslice]
// ---------------------------------------------------------------------------
__global__ void qk_kernel() {
    int n = blockIdx.z, i0 = blockIdx.y * 32, j0 = blockIdx.x * 32;
    int t = threadIdx.x;
    __shared__ float Qs[32][33], Ks[32][33];
    for (int l = t; l < 1024; l += 256) {
        int r = l >> 5, d = l & 31;
        Qs[r][d] = g_q[(i0 + r)*DE + n*DH + d];
        Ks[r][d] = g_k[(j0 + r)*DE + n*DH + d];
    }
    __syncthreads();
    int tx = t & 31, ty = t >> 5;
    float acc[4] = {0.f, 0.f, 0.f, 0.f};
    #pragma unroll
    for (int d = 0; d < 32; d++) {
        float kv = Ks[tx][d];
        #pragma unroll
        for (int m = 0; m < 4; m++) acc[m] = fmaf(Qs[ty*4 + m][d], kv, acc[m]);
    }
    #pragma unroll
    for (int m = 0; m < 4; m++)
        g_sc[((size_t)(i0 + ty*4 + m)*L + (j0 + tx))*NH + n] = acc[m] * SCALE;
}

// ---------------------------------------------------------------------------
// Kernel 3: fully fused attention + output projection. 1 CTA per query i.
// Phase A: scores (warp=8 j's, e read once, all heads in regs)
// Phase B: per-head online softmax + attn@v (warp=head)
// Phase C: edge-weight accumulation (warp=8 j's, e read once, heads in regs)
// Tail:    cross-warp reductions, edge proj, @Wo + bo -> out.
// ---------------------------------------------------------------------------
__global__ void attn_kernel(const float* __restrict__ e, const float* __restrict__ We,
                            const float* __restrict__ Wo, const float* __restrict__ bo,
                            float* __restrict__ out) {
    int i = blockIdx.x, t = threadIdx.x;
    int w = t >> 5, lane = t & 31;
    int jg = lane >> 2, cq = lane & 3;

    __shared__ __align__(16) float ps[512];
    __shared__ __align__(16) float es[64][68];   // row stride 68 floats (17 float4)
    __shared__ float scs[NH][64];
    __shared__ float pes[NH][64];
    __shared__ float alphas[NH];
    __shared__ float svals[NH];
    __shared__ float wpart[8][NH][64];           // [src warp][head][c]  16 KB
    __shared__ float wfin[NH][64];
    __shared__ float att[DE];
    __shared__ float opart[4][64];

    ps[t]       = g_p[i*512 + t];
    ps[t + 256] = g_p[i*512 + t + 256];

    float m = -1e30f, s = 0.f, vac = 0.f;
    float wacc[8][2];
    #pragma unroll
    for (int n = 0; n < 8; n++) { wacc[n][0] = 0.f; wacc[n][1] = 0.f; }

    const float4* esrc = (const float4*)&e[(size_t)i*L*DO];  // 16 float4 per j-row
    float4 buf[4];
    #pragma unroll
    for (int k = 0; k < 4; k++) buf[k] = esrc[t + k*256];

    for (int j0 = 0; j0 < L; j0 += 64) {
        __syncthreads();                 // prev phase C done with es (ps ready on iter 0)
        #pragma unroll
        for (int k = 0; k < 4; k++) {
            int l = t + k*256, jj = l >> 4, c4 = (l & 15) * 4;
            es[jj][c4 + 0] = buf[k].x; es[jj][c4 + 1] = buf[k].y;
            es[jj][c4 + 2] = buf[k].z; es[jj][c4 + 3] = buf[k].w;
        }
        __syncthreads();
        if (j0 + 64 < L) {               // prefetch next tile during compute
            #pragma unroll
            for (int k = 0; k < 4; k++) buf[k] = esrc[(j0 + 64)*16 + t + k*256];
        }

        // ---------------- Phase A: scores. j = j0 + w*8 + jg, quarter cq.
        {
            int jl = w*8 + jg;
            const float4* erow = (const float4*)&es[jl][0];
            float4 ev0 = erow[cq*4 + 0], ev1 = erow[cq*4 + 1];
            float4 ev2 = erow[cq*4 + 2], ev3 = erow[cq*4 + 3];
            const float4* psf4 = (const float4*)ps;
            float acc[8];
            #pragma unroll
            for (int n = 0; n < 8; n++) {
                float4 p0 = psf4[n*16 + cq*4 + 0];
                float4 p1 = psf4[n*16 + cq*4 + 1];
                float4 p2 = psf4[n*16 + cq*4 + 2];
                float4 p3 = psf4[n*16 + cq*4 + 3];
                float a = 0.f;
                a = fmaf(ev0.x, p0.x, a); a = fmaf(ev0.y, p0.y, a);
                a = fmaf(ev0.z, p0.z, a); a = fmaf(ev0.w, p0.w, a);
                a = fmaf(ev1.x, p1.x, a); a = fmaf(ev1.y, p1.y, a);
                a = fmaf(ev1.z, p1.z, a); a = fmaf(ev1.w, p1.w, a);
                a = fmaf(ev2.x, p2.x, a); a = fmaf(ev2.y, p2.y, a);
                a = fmaf(ev2.z, p2.z, a); a = fmaf(ev2.w, p2.w, a);
                a = fmaf(ev3.x, p3.x, a); a = fmaf(ev3.y, p3.y, a);
                a = fmaf(ev3.z, p3.z, a); a = fmaf(ev3.w, p3.w, a);
                acc[n] = a;
            }
            #pragma unroll
            for (int off = 1; off <= 2; off <<= 1)
                #pragma unroll
                for (int n = 0; n < 8; n++)
                    acc[n] += __shfl_xor_sync(0xffffffffu, acc[n], off);
            if (cq == 0) {
                int j = j0 + jl;
                const float4* scb = (const float4*)&g_sc[((size_t)i*L + j)*NH];
                float4 b0 = scb[0], b1 = scb[1];
                scs[0][jl] = acc[0] + b0.x; scs[1][jl] = acc[1] + b0.y;
                scs[2][jl] = acc[2] + b0.z; scs[3][jl] = acc[3] + b0.w;
                scs[4][jl] = acc[4] + b1.x; scs[5][jl] = acc[5] + b1.y;
                scs[6][jl] = acc[6] + b1.z; scs[7][jl] = acc[7] + b1.w;
            }
        }
        __syncthreads();

        // ---------------- Phase B: head w online softmax + attn@v
        {
            float sc0 = scs[w][lane], sc1 = scs[w][lane + 32];
            float bm = fmaxf(sc0, sc1);
            #pragma unroll
            for (int off = 16; off; off >>= 1)
                bm = fmaxf(bm, __shfl_xor_sync(0xffffffffu, bm, off));
            float newm = fmaxf(m, bm);
            float alpha = __expf(m - newm);
            s *= alpha; vac *= alpha;
            float pe0 = __expf(sc0 - newm), pe1 = __expf(sc1 - newm);
            pes[w][lane] = pe0; pes[w][lane + 32] = pe1;
            float bs = pe0 + pe1;
            #pragma unroll
            for (int off = 16; off; off >>= 1)
                bs += __shfl_xor_sync(0xffffffffu, bs, off);
            s += bs;
            m = newm;
            if (lane == 0) alphas[w] = alpha;
            __syncwarp();
            const float* vb = &g_v[(size_t)j0*DE + w*DH + lane];
            #pragma unroll 8
            for (int jj = 0; jj < 64; jj++)
                vac = fmaf(pes[w][jj], vb[jj*DE], vac);
        }
        __syncthreads();

        // ---------------- Phase C: edge-weight accumulation, j-slice of warp w
        {
            #pragma unroll
            for (int n = 0; n < 8; n++) {
                float a = alphas[n];
                wacc[n][0] *= a; wacc[n][1] *= a;
            }
            #pragma unroll
            for (int jj = w*8; jj < w*8 + 8; jj++) {
                float2 ev2 = *(const float2*)&es[jj][2*lane];
                #pragma unroll
                for (int n = 0; n < 8; n++) {
                    float pv = pes[n][jj];
                    wacc[n][0] = fmaf(pv, ev2.x, wacc[n][0]);
                    wacc[n][1] = fmaf(pv, ev2.y, wacc[n][1]);
                }
            }
        }
    }

    // ---------------- Tail: reductions + output projection
    #pragma unroll
    for (int n = 0; n < 8; n++) {
        wpart[w][n][2*lane]     = wacc[n][0];
        wpart[w][n][2*lane + 1] = wacc[n][1];
    }
    if (lane == 0) svals[w] = s;
    __syncthreads();

    {   // reduce edge-weight partials across 8 warps (thread t -> 2 entries)
        int n0 = t >> 6, c0 = t & 63;
        int n1 = n0 + 4;
        float f0 = 0.f, f1 = 0.f;
        #pragma unroll
        for (int sw = 0; sw < 8; sw++) {
            f0 += wpart[sw][n0][c0];
            f1 += wpart[sw][n1][c0];
        }
        wfin[n0][c0] = f0; wfin[n1][c0] = f1;
    }
    __syncthreads();

    {   // att[t] = (attn@v + edge proj)/s
        int n = t >> 5;
        float edge = 0.f;
        const float* wn = &wfin[n][0];
        #pragma unroll
        for (int c = 0; c < 64; c++) edge = fmaf(wn[c], We[c*DE + t], edge);
        att[t] = (vac + edge) / svals[n];
    }
    __syncthreads();

    {   // out = att@Wo + bo : 64 outputs x 4-way k-split
        int o = t & 63, kq = t >> 6;
        float a = 0.f;
        #pragma unroll
        for (int kk = 0; kk < 64; kk++) {
            int k = kq*64 + kk;
            a = fmaf(att[k], Wo[k*DO + o], a);
        }
        opart[kq][o] = a;
    }
    __syncthreads();
    if (t < DO) {
        out[i*DO + t] = bo[t] + opart[0][t] + opart[1][t] + opart[2][t] + opart[3][t];
    }
}

// ---------------------------------------------------------------------------
extern "C" void kernel_launch(void* const* d_in, const int* in_sizes, int n_in,
                              void* d_out, int out_size) {
    const float* x  = (const float*)d_in[0];
    const float* e  = (const float*)d_in[1];
    const float* Wq = (const float*)d_in[2];
    const float* Wk = (const float*)d_in[3];
    const float* Wv = (const float*)d_in[4];
    const float* We = (const float*)d_in[5];
    const float* Wo = (const float*)d_in[6];
    const float* bo = (const float*)d_in[7];
    float* out = (float*)d_out;

    proj_kernel<<<512, 256>>>(x, Wq, Wk, Wv, We);
    qk_kernel<<<dim3(16, 16, 8), 256>>>();
    attn_kernel<<<512, 256>>>(e, We, Wo, bo, out);
}

// round 4
// speedup vs baseline: 1.6896x; 1.6896x over previous
#include <cuda_runtime.h>
#include <math.h>

#define L 512
#define DO 64      // D_ORIG
#define NH 8
#define DH 32
#define DE 256
#define SCALE 0.17677669529663687f  // 1/sqrt(32)

// Scratch (device globals — no allocations allowed)
__device__ float g_q[L*DE];
__device__ float g_k[L*DE];
__device__ float g_v[L*DE];
__device__ float g_p[L*512];            // [i][n*64+c], SCALE folded in
__device__ float g_sc[(size_t)NH*L*L];  // [n][i][j] base qk logits (SCALE folded)

// ---------------------------------------------------------------------------
// Kernel 1: tiled GEMM  {q,k,v}[512x256] = x[512x64] @ W[64x256]
// grid (4 col-tiles, 8 row-tiles, 3 matrices), 256 thr, 16 outputs/thread.
// ---------------------------------------------------------------------------
__global__ void proj_kernel(const float* __restrict__ x, const float* __restrict__ Wq,
                            const float* __restrict__ Wk, const float* __restrict__ Wv) {
    const float* W = (blockIdx.z == 0) ? Wq : (blockIdx.z == 1) ? Wk : Wv;
    float* outp    = (blockIdx.z == 0) ? g_q : (blockIdx.z == 1) ? g_k : g_v;
    int c0 = blockIdx.x * 64, i0 = blockIdx.y * 64;
    int t = threadIdx.x;
    __shared__ __align__(16) float xs[64][68];
    __shared__ __align__(16) float ws[64][68];
    for (int l = t; l < 1024; l += 256) {
        int r = l >> 4, c4 = (l & 15) * 4;
        *(float4*)&xs[r][c4] = *(const float4*)&x[(i0 + r)*DO + c4];
        *(float4*)&ws[r][c4] = *(const float4*)&W[r*DE + c0 + c4];
    }
    __syncthreads();
    int ty = t >> 4, tx = t & 15;    // 16x16 threads, 4x4 micro-tile
    float acc[4][4] = {};
    #pragma unroll
    for (int k = 0; k < 64; k++) {
        float4 b = *(const float4*)&ws[k][tx*4];
        float a0 = xs[ty*4+0][k], a1 = xs[ty*4+1][k], a2 = xs[ty*4+2][k], a3 = xs[ty*4+3][k];
        acc[0][0] = fmaf(a0, b.x, acc[0][0]); acc[0][1] = fmaf(a0, b.y, acc[0][1]);
        acc[0][2] = fmaf(a0, b.z, acc[0][2]); acc[0][3] = fmaf(a0, b.w, acc[0][3]);
        acc[1][0] = fmaf(a1, b.x, acc[1][0]); acc[1][1] = fmaf(a1, b.y, acc[1][1]);
        acc[1][2] = fmaf(a1, b.z, acc[1][2]); acc[1][3] = fmaf(a1, b.w, acc[1][3]);
        acc[2][0] = fmaf(a2, b.x, acc[2][0]); acc[2][1] = fmaf(a2, b.y, acc[2][1]);
        acc[2][2] = fmaf(a2, b.z, acc[2][2]); acc[2][3] = fmaf(a2, b.w, acc[2][3]);
        acc[3][0] = fmaf(a3, b.x, acc[3][0]); acc[3][1] = fmaf(a3, b.y, acc[3][1]);
        acc[3][2] = fmaf(a3, b.z, acc[3][2]); acc[3][3] = fmaf(a3, b.w, acc[3][3]);
    }
    #pragma unroll
    for (int m = 0; m < 4; m++)
        *(float4*)&outp[(i0 + ty*4 + m)*DE + c0 + tx*4] = *(float4*)&acc[m][0];
}

// ---------------------------------------------------------------------------
// Kernel 1b: p[i][n*64+c] = SCALE * sum_d q[i][n*32+d] * We[c][n*32+d]
// grid (8 i-tiles, 8 heads), K=32 GEMM per head.
// ---------------------------------------------------------------------------
__global__ void p_kernel(const float* __restrict__ We) {
    int i0 = blockIdx.x * 64, n = blockIdx.y;
    int t = threadIdx.x;
    __shared__ __align__(16) float qs[64][36];
    __shared__ __align__(16) float wes[32][68];
    for (int l = t; l < 512; l += 256) {      // q tile: 64 rows x 32 d
        int r = l >> 3, d4 = (l & 7) * 4;
        *(float4*)&qs[r][d4] = *(const float4*)&g_q[(i0 + r)*DE + n*DH + d4];
    }
    for (int l = t; l < 512; l += 256) {      // We tile, transposed to [d][c]
        int c = l >> 3, d4 = (l & 7) * 4;
        float4 v4 = *(const float4*)&We[c*DE + n*DH + d4];
        wes[d4 + 0][c] = v4.x; wes[d4 + 1][c] = v4.y;
        wes[d4 + 2][c] = v4.z; wes[d4 + 3][c] = v4.w;
    }
    __syncthreads();
    int ty = t >> 4, tx = t & 15;
    float acc[4][4] = {};
    #pragma unroll
    for (int d = 0; d < 32; d++) {
        float4 b = *(const float4*)&wes[d][tx*4];
        float a0 = qs[ty*4+0][d], a1 = qs[ty*4+1][d], a2 = qs[ty*4+2][d], a3 = qs[ty*4+3][d];
        acc[0][0] = fmaf(a0, b.x, acc[0][0]); acc[0][1] = fmaf(a0, b.y, acc[0][1]);
        acc[0][2] = fmaf(a0, b.z, acc[0][2]); acc[0][3] = fmaf(a0, b.w, acc[0][3]);
        acc[1][0] = fmaf(a1, b.x, acc[1][0]); acc[1][1] = fmaf(a1, b.y, acc[1][1]);
        acc[1][2] = fmaf(a1, b.z, acc[1][2]); acc[1][3] = fmaf(a1, b.w, acc[1][3]);
        acc[2][0] = fmaf(a2, b.x, acc[2][0]); acc[2][1] = fmaf(a2, b.y, acc[2][1]);
        acc[2][2] = fmaf(a2, b.z, acc[2][2]); acc[2][3] = fmaf(a2, b.w, acc[2][3]);
        acc[3][0] = fmaf(a3, b.x, acc[3][0]); acc[3][1] = fmaf(a3, b.y, acc[3][1]);
        acc[3][2] = fmaf(a3, b.z, acc[3][2]); acc[3][3] = fmaf(a3, b.w, acc[3][3]);
    }
    #pragma unroll
    for (int m = 0; m < 4; m++) {
        #pragma unroll
        for (int j = 0; j < 4; j++) acc[m][j] *= SCALE;
        *(float4*)&g_p[(i0 + ty*4 + m)*512 + n*64 + tx*4] = *(float4*)&acc[m][0];
    }
}

// ---------------------------------------------------------------------------
// Kernel 2: base[n][i][j] = scale * q[i,nslice] . k[j,nslice]
// ---------------------------------------------------------------------------
__global__ void qk_kernel() {
    int n = blockIdx.z, i0 = blockIdx.y * 32, j0 = blockIdx.x * 32;
    int t = threadIdx.x;
    __shared__ float Qs[32][33], Ks[32][33];
    for (int l = t; l < 1024; l += 256) {
        int r = l >> 5, d = l & 31;
        Qs[r][d] = g_q[(i0 + r)*DE + n*DH + d];
        Ks[r][d] = g_k[(j0 + r)*DE + n*DH + d];
    }
    __syncthreads();
    int tx = t & 31, ty = t >> 5;
    float acc[4] = {0.f, 0.f, 0.f, 0.f};
    #pragma unroll
    for (int d = 0; d < 32; d++) {
        float kv = Ks[tx][d];
        #pragma unroll
        for (int m = 0; m < 4; m++) acc[m] = fmaf(Qs[ty*4 + m][d], kv, acc[m]);
    }
    #pragma unroll
    for (int m = 0; m < 4; m++)
        g_sc[((size_t)n*L + (i0 + ty*4 + m))*L + j0 + tx] = acc[m] * SCALE;
}

// ---------------------------------------------------------------------------
// Kernel 3 (hot): fused edge logits + online softmax + edge-weight accum +
// attn@v + FULL OUTPUT PROJECTION. 1 CTA per query i, warp w = head w.
// ---------------------------------------------------------------------------
__global__ void attn_kernel(const float* __restrict__ e, const float* __restrict__ We,
                            const float* __restrict__ Wo, const float* __restrict__ bo,
                            float* __restrict__ out) {
    int i = blockIdx.x, t = threadIdx.x;
    int w = t >> 5, lane = t & 31;
    __shared__ float ps[512];
    __shared__ float es[64][65];     // pad 65: conflict-free rows AND columns
    __shared__ float pes[8][64];
    __shared__ float wfin[NH][64];
    __shared__ float svals[NH];
    __shared__ float att[DE];
    __shared__ float opart[4][64];

    ps[t]       = g_p[i*512 + t];
    ps[t + 256] = g_p[i*512 + t + 256];

    float m = -1e30f, s = 0.f, wlo = 0.f, whi = 0.f, vac = 0.f;
    const float* pn = &ps[w*64];
    const float4* esrc = (const float4*)&e[(size_t)i*L*DO];

    float4 buf[4];
    #pragma unroll
    for (int k = 0; k < 4; k++) buf[k] = esrc[t + k*256];

    for (int j0 = 0; j0 < L; j0 += 64) {
        __syncthreads();
        #pragma unroll
        for (int k = 0; k < 4; k++) {
            int l = t + k*256, jj = l >> 4, c4 = (l & 15) * 4;
            es[jj][c4 + 0] = buf[k].x; es[jj][c4 + 1] = buf[k].y;
            es[jj][c4 + 2] = buf[k].z; es[jj][c4 + 3] = buf[k].w;
        }
        __syncthreads();
        if (j0 + 64 < L) {
            #pragma unroll
            for (int k = 0; k < 4; k++) buf[k] = esrc[(j0 + 64)*16 + t + k*256];
        }

        // ---- edge logits for j = j0+lane, j0+lane+32 (2 partial accums each)
        size_t base = ((size_t)w*L + i)*L + j0;
        float sc0 = g_sc[base + lane];
        float sc1 = g_sc[base + lane + 32];
        float a0 = 0.f, b0 = 0.f, a1 = 0.f, b1 = 0.f;
        #pragma unroll
        for (int c = 0; c < 64; c += 2) {
            float p0 = pn[c], p1 = pn[c + 1];
            a0 = fmaf(es[lane][c],          p0, a0);
            b0 = fmaf(es[lane][c + 1],      p1, b0);
            a1 = fmaf(es[lane + 32][c],     p0, a1);
            b1 = fmaf(es[lane + 32][c + 1], p1, b1);
        }
        sc0 += a0 + b0; sc1 += a1 + b1;

        // ---- online softmax (per-warp)
        float bm = fmaxf(sc0, sc1);
        #pragma unroll
        for (int off = 16; off; off >>= 1) bm = fmaxf(bm, __shfl_xor_sync(0xffffffffu, bm, off));
        float newm = fmaxf(m, bm);
        float alpha = __expf(m - newm);
        s *= alpha; wlo *= alpha; whi *= alpha; vac *= alpha;
        float pe0 = __expf(sc0 - newm), pe1 = __expf(sc1 - newm);
        pes[w][lane] = pe0; pes[w][lane + 32] = pe1;
        float bs = pe0 + pe1;
        #pragma unroll
        for (int off = 16; off; off >>= 1) bs += __shfl_xor_sync(0xffffffffu, bs, off);
        s += bs;
        m = newm;
        __syncwarp();

        // ---- accumulate edge-weights AND attn@v (v is L2/L1-resident)
        const float* vb = &g_v[(size_t)j0*DE + w*DH + lane];
        #pragma unroll 8
        for (int jj = 0; jj < 64; jj++) {
            float pv = pes[w][jj];
            wlo = fmaf(pv, es[jj][lane],      wlo);
            whi = fmaf(pv, es[jj][lane + 32], whi);
            vac = fmaf(pv, vb[jj*DE],         vac);
        }
    }

    // ---------------- Tail: edge projection + output projection (fused out)
    wfin[w][lane]      = wlo;
    wfin[w][lane + 32] = whi;
    if (lane == 0) svals[w] = s;
    __syncthreads();

    {   // att[t] = (attn@v + edge proj)/s   (col t belongs to head t>>5; vac IS col t)
        int n = t >> 5;
        float edge0 = 0.f, edge1 = 0.f;
        const float* wn = &wfin[n][0];
        #pragma unroll
        for (int c = 0; c < 64; c += 2) {
            edge0 = fmaf(wn[c],     We[c*DE + t],       edge0);
            edge1 = fmaf(wn[c + 1], We[(c + 1)*DE + t], edge1);
        }
        att[t] = (vac + edge0 + edge1) / svals[n];
    }
    __syncthreads();

    {   // out = att@Wo + bo : 64 outputs x 4-way k-split
        int o = t & 63, kq = t >> 6;
        float a = 0.f;
        #pragma unroll
        for (int kk = 0; kk < 64; kk++) {
            int k = kq*64 + kk;
            a = fmaf(att[k], Wo[k*DO + o], a);
        }
        opart[kq][o] = a;
    }
    __syncthreads();
    if (t < DO)
        out[i*DO + t] = bo[t] + opart[0][t] + opart[1][t] + opart[2][t] + opart[3][t];
}

// ---------------------------------------------------------------------------
extern "C" void kernel_launch(void* const* d_in, const int* in_sizes, int n_in,
                              void* d_out, int out_size) {
    const float* x  = (const float*)d_in[0];
    const float* e  = (const float*)d_in[1];
    const float* Wq = (const float*)d_in[2];
    const float* Wk = (const float*)d_in[3];
    const float* Wv = (const float*)d_in[4];
    const float* We = (const float*)d_in[5];
    const float* Wo = (const float*)d_in[6];
    const float* bo = (const float*)d_in[7];
    float* out = (float*)d_out;

    proj_kernel<<<dim3(4, 8, 3), 256>>>(x, Wq, Wk, Wv);
    p_kernel<<<dim3(8, 8), 256>>>(We);
    qk_kernel<<<dim3(16, 16, 8), 256>>>();
    attn_kernel<<<512, 256>>>(e, We, Wo, bo, out);
}

// round 6
// speedup vs baseline: 1.7632x; 1.0436x over previous
#include <cuda_runtime.h>
#include <stdint.h>
#include <math.h>

#define L 512
#define DO 64      // D_ORIG
#define NH 8
#define DH 32
#define DE 256
#define SCALE 0.17677669529663687f  // 1/sqrt(32)

// Scratch (device globals — no allocations allowed)
__device__ float g_q[L*DE];
__device__ float g_k[L*DE];
__device__ float g_v[L*DE];
__device__ float g_p[L*512];            // [i][n*64+c], SCALE folded in
__device__ float g_sc[(size_t)NH*L*L];  // [n][i][j] base qk logits (SCALE folded)

#define CP_ASYNC16(sa, ga) asm volatile("cp.async.cg.shared.global [%0], [%1], 16;\n" :: "r"(sa), "l"(ga))
#define CP_COMMIT()        asm volatile("cp.async.commit_group;\n" ::: "memory")
#define CP_WAIT0()         asm volatile("cp.async.wait_group 0;\n" ::: "memory")

// ---------------------------------------------------------------------------
// Kernel 1: tiled GEMM  {q,k,v}[512x256] = x[512x64] @ W[64x256]
// ---------------------------------------------------------------------------
__global__ void proj_kernel(const float* __restrict__ x, const float* __restrict__ Wq,
                            const float* __restrict__ Wk, const float* __restrict__ Wv) {
    const float* W = (blockIdx.z == 0) ? Wq : (blockIdx.z == 1) ? Wk : Wv;
    float* outp    = (blockIdx.z == 0) ? g_q : (blockIdx.z == 1) ? g_k : g_v;
    int c0 = blockIdx.x * 64, i0 = blockIdx.y * 64;
    int t = threadIdx.x;
    __shared__ __align__(16) float xs[64][68];
    __shared__ __align__(16) float ws[64][68];
    for (int l = t; l < 1024; l += 256) {
        int r = l >> 4, c4 = (l & 15) * 4;
        *(float4*)&xs[r][c4] = *(const float4*)&x[(i0 + r)*DO + c4];
        *(float4*)&ws[r][c4] = *(const float4*)&W[r*DE + c0 + c4];
    }
    __syncthreads();
    int ty = t >> 4, tx = t & 15;
    float acc[4][4] = {};
    #pragma unroll
    for (int k = 0; k < 64; k++) {
        float4 b = *(const float4*)&ws[k][tx*4];
        float a0 = xs[ty*4+0][k], a1 = xs[ty*4+1][k], a2 = xs[ty*4+2][k], a3 = xs[ty*4+3][k];
        acc[0][0] = fmaf(a0, b.x, acc[0][0]); acc[0][1] = fmaf(a0, b.y, acc[0][1]);
        acc[0][2] = fmaf(a0, b.z, acc[0][2]); acc[0][3] = fmaf(a0, b.w, acc[0][3]);
        acc[1][0] = fmaf(a1, b.x, acc[1][0]); acc[1][1] = fmaf(a1, b.y, acc[1][1]);
        acc[1][2] = fmaf(a1, b.z, acc[1][2]); acc[1][3] = fmaf(a1, b.w, acc[1][3]);
        acc[2][0] = fmaf(a2, b.x, acc[2][0]); acc[2][1] = fmaf(a2, b.y, acc[2][1]);
        acc[2][2] = fmaf(a2, b.z, acc[2][2]); acc[2][3] = fmaf(a2, b.w, acc[2][3]);
        acc[3][0] = fmaf(a3, b.x, acc[3][0]); acc[3][1] = fmaf(a3, b.y, acc[3][1]);
        acc[3][2] = fmaf(a3, b.z, acc[3][2]); acc[3][3] = fmaf(a3, b.w, acc[3][3]);
    }
    #pragma unroll
    for (int m = 0; m < 4; m++)
        *(float4*)&outp[(i0 + ty*4 + m)*DE + c0 + tx*4] = *(float4*)&acc[m][0];
}

// ---------------------------------------------------------------------------
// Kernel 1b: p[i][n*64+c] = SCALE * sum_d q[i][n*32+d] * We[c][n*32+d]
// ---------------------------------------------------------------------------
__global__ void p_kernel(const float* __restrict__ We) {
    int i0 = blockIdx.x * 64, n = blockIdx.y;
    int t = threadIdx.x;
    __shared__ __align__(16) float qs[64][36];
    __shared__ __align__(16) float wes[32][68];
    for (int l = t; l < 512; l += 256) {
        int r = l >> 3, d4 = (l & 7) * 4;
        *(float4*)&qs[r][d4] = *(const float4*)&g_q[(i0 + r)*DE + n*DH + d4];
    }
    for (int l = t; l < 512; l += 256) {
        int c = l >> 3, d4 = (l & 7) * 4;
        float4 v4 = *(const float4*)&We[c*DE + n*DH + d4];
        wes[d4 + 0][c] = v4.x; wes[d4 + 1][c] = v4.y;
        wes[d4 + 2][c] = v4.z; wes[d4 + 3][c] = v4.w;
    }
    __syncthreads();
    int ty = t >> 4, tx = t & 15;
    float acc[4][4] = {};
    #pragma unroll
    for (int d = 0; d < 32; d++) {
        float4 b = *(const float4*)&wes[d][tx*4];
        float a0 = qs[ty*4+0][d], a1 = qs[ty*4+1][d], a2 = qs[ty*4+2][d], a3 = qs[ty*4+3][d];
        acc[0][0] = fmaf(a0, b.x, acc[0][0]); acc[0][1] = fmaf(a0, b.y, acc[0][1]);
        acc[0][2] = fmaf(a0, b.z, acc[0][2]); acc[0][3] = fmaf(a0, b.w, acc[0][3]);
        acc[1][0] = fmaf(a1, b.x, acc[1][0]); acc[1][1] = fmaf(a1, b.y, acc[1][1]);
        acc[1][2] = fmaf(a1, b.z, acc[1][2]); acc[1][3] = fmaf(a1, b.w, acc[1][3]);
        acc[2][0] = fmaf(a2, b.x, acc[2][0]); acc[2][1] = fmaf(a2, b.y, acc[2][1]);
        acc[2][2] = fmaf(a2, b.z, acc[2][2]); acc[2][3] = fmaf(a2, b.w, acc[2][3]);
        acc[3][0] = fmaf(a3, b.x, acc[3][0]); acc[3][1] = fmaf(a3, b.y, acc[3][1]);
        acc[3][2] = fmaf(a3, b.z, acc[3][2]); acc[3][3] = fmaf(a3, b.w, acc[3][3]);
    }
    #pragma unroll
    for (int m = 0; m < 4; m++) {
        #pragma unroll
        for (int j = 0; j < 4; j++) acc[m][j] *= SCALE;
        *(float4*)&g_p[(i0 + ty*4 + m)*512 + n*64 + tx*4] = *(float4*)&acc[m][0];
    }
}

// ---------------------------------------------------------------------------
// Kernel 2: base[n][i][j] = scale * q[i,nslice] . k[j,nslice]
// ---------------------------------------------------------------------------
__global__ void qk_kernel() {
    int n = blockIdx.z, i0 = blockIdx.y * 32, j0 = blockIdx.x * 32;
    int t = threadIdx.x;
    __shared__ float Qs[32][33], Ks[32][33];
    for (int l = t; l < 1024; l += 256) {
        int r = l >> 5, d = l & 31;
        Qs[r][d] = g_q[(i0 + r)*DE + n*DH + d];
        Ks[r][d] = g_k[(j0 + r)*DE + n*DH + d];
    }
    __syncthreads();
    int tx = t & 31, ty = t >> 5;
    float acc[4] = {0.f, 0.f, 0.f, 0.f};
    #pragma unroll
    for (int d = 0; d < 32; d++) {
        float kv = Ks[tx][d];
        #pragma unroll
        for (int m = 0; m < 4; m++) acc[m] = fmaf(Qs[ty*4 + m][d], kv, acc[m]);
    }
    #pragma unroll
    for (int m = 0; m < 4; m++)
        g_sc[((size_t)n*L + (i0 + ty*4 + m))*L + j0 + tx] = acc[m] * SCALE;
}

// ---------------------------------------------------------------------------
// Kernel 3 (hot): fused attention + output projection, cp.async double-buffer.
// 1 CTA per query i. Warp w = head w (scores/softmax/edge-weights).
// attn@v: thread owns d-quad 4*(t&63), jj-part t>>6 (16 jj), LDG.128.
// ---------------------------------------------------------------------------
__global__ void __launch_bounds__(256, 5)
attn_kernel(const float* __restrict__ e, const float* __restrict__ We,
            const float* __restrict__ Wo, const float* __restrict__ bo,
            float* __restrict__ out) {
    int i = blockIdx.x, t = threadIdx.x;
    int w = t >> 5, lane = t & 31;
    int t63 = t & 63;
    int vh = t63 >> 3;              // head for attn@v accumulation
    int vpart = t >> 6;             // jj-quarter

    // es tiles: [2][64][68] floats. Row reads (float4) and column reads both
    // conflict-free with stride 68. Tail arrays overlay buffer 0.
    __shared__ __align__(16) float espool[2*4352];
    __shared__ __align__(16) float ps[512];
    __shared__ float pes[NH][64];
    __shared__ float alphas[NH];
    __shared__ float svals[NH];

    const float* ebase = e + (size_t)i*L*DO;

    // prologue: tile 0 -> buffer 0 via cp.async
    #pragma unroll
    for (int k2 = 0; k2 < 4; k2++) {
        int l = t + k2*256;                 // float4 index in 64x64 tile
        int jj = l >> 4, c4 = (l & 15) * 4;
        unsigned int sa = (unsigned int)__cvta_generic_to_shared(&espool[jj*68 + c4]);
        CP_ASYNC16(sa, ebase + (size_t)l*4);
    }
    CP_COMMIT();

    ps[t]       = g_p[i*512 + t];
    ps[t + 256] = g_p[i*512 + t + 256];

    float m = -1e30f, s = 0.f, wlo = 0.f, whi = 0.f;
    float4 vac = make_float4(0.f, 0.f, 0.f, 0.f);
    const float4* pf = (const float4*)&ps[w*64];

    for (int tile = 0; tile < 8; tile++) {
        int b = tile & 1, j0 = tile * 64;
        CP_WAIT0();
        __syncthreads();   // es[b] ready; prev tile's accum done

        if (tile < 7) {    // prefetch next tile into other buffer
            #pragma unroll
            for (int k2 = 0; k2 < 4; k2++) {
                int l = t + k2*256;
                int jj = l >> 4, c4 = (l & 15) * 4;
                unsigned int sa = (unsigned int)__cvta_generic_to_shared(&espool[(b^1)*4352 + jj*68 + c4]);
                CP_ASYNC16(sa, ebase + (size_t)(j0 + 64)*64 + (size_t)l*4);
            }
            CP_COMMIT();
        }

        // ---- edge logits for head w, j = j0+lane / j0+lane+32 (float4 rows)
        const float4* r0 = (const float4*)&espool[b*4352 + lane*68];
        const float4* r1 = (const float4*)&espool[b*4352 + (lane + 32)*68];
        size_t scb = ((size_t)w*L + i)*L + j0;
        float sc0 = g_sc[scb + lane];
        float sc1 = g_sc[scb + lane + 32];
        float s00 = 0.f, s01 = 0.f, s10 = 0.f, s11 = 0.f;
        #pragma unroll
        for (int c = 0; c < 16; c += 2) {
            float4 p0 = pf[c], p1 = pf[c + 1];
            float4 e00 = r0[c], e01 = r0[c + 1], e10 = r1[c], e11 = r1[c + 1];
            s00 = fmaf(e00.x, p0.x, s00); s00 = fmaf(e00.y, p0.y, s00);
            s00 = fmaf(e00.z, p0.z, s00); s00 = fmaf(e00.w, p0.w, s00);
            s01 = fmaf(e01.x, p1.x, s01); s01 = fmaf(e01.y, p1.y, s01);
            s01 = fmaf(e01.z, p1.z, s01); s01 = fmaf(e01.w, p1.w, s01);
            s10 = fmaf(e10.x, p0.x, s10); s10 = fmaf(e10.y, p0.y, s10);
            s10 = fmaf(e10.z, p0.z, s10); s10 = fmaf(e10.w, p0.w, s10);
            s11 = fmaf(e11.x, p1.x, s11); s11 = fmaf(e11.y, p1.y, s11);
            s11 = fmaf(e11.z, p1.z, s11); s11 = fmaf(e11.w, p1.w, s11);
        }
        sc0 += s00 + s01; sc1 += s10 + s11;

        // ---- online softmax (per-warp = per-head)
        float bm = fmaxf(sc0, sc1);
        #pragma unroll
        for (int off = 16; off; off >>= 1) bm = fmaxf(bm, __shfl_xor_sync(0xffffffffu, bm, off));
        float newm = fmaxf(m, bm);
        float alpha = __expf(m - newm);
        s *= alpha; wlo *= alpha; whi *= alpha;
        float pe0 = __expf(sc0 - newm), pe1 = __expf(sc1 - newm);
        pes[w][lane] = pe0; pes[w][lane + 32] = pe1;
        float bs = pe0 + pe1;
        #pragma unroll
        for (int off = 16; off; off >>= 1) bs += __shfl_xor_sync(0xffffffffu, bs, off);
        s += bs;
        m = newm;
        if (lane == 0) alphas[w] = alpha;
        __syncthreads();   // pes/alphas visible CTA-wide

        // ---- attn@v : d-quad per thread, 16 jj's, coalesced LDG.128
        {
            float av = alphas[vh];
            vac.x *= av; vac.y *= av; vac.z *= av; vac.w *= av;
            const float* vrow = &g_v[(size_t)(j0 + vpart*16)*DE + 4*t63];
            const float* pv16 = &pes[vh][vpart*16];
            #pragma unroll
            for (int q = 0; q < 16; q++) {
                float pv = pv16[q];
                float4 vv = *(const float4*)&vrow[(size_t)q*DE];
                vac.x = fmaf(pv, vv.x, vac.x); vac.y = fmaf(pv, vv.y, vac.y);
                vac.z = fmaf(pv, vv.z, vac.z); vac.w = fmaf(pv, vv.w, vac.w);
            }
        }

        // ---- edge-weight accumulation (head w, columns lane / lane+32)
        {
            const float* pw = &pes[w][0];
            const float* ecol = &espool[b*4352];
            #pragma unroll 16
            for (int jj = 0; jj < 64; jj++) {
                float pv = pw[jj];
                wlo = fmaf(pv, ecol[jj*68 + lane],      wlo);
                whi = fmaf(pv, ecol[jj*68 + lane + 32], whi);
            }
        }
    }

    // ---------------- Tail (overlay buffer 0 of espool; tile 7 used buffer 1)
    float* wfin  = espool;          // [8][64]  = 512 floats
    float* vred  = espool + 512;    // [4][256] = 1024 floats
    float* att   = espool + 1536;   // [256]
    float* opart = espool + 1792;   // [4][64]  = 256 floats

    wfin[w*64 + lane]      = wlo;
    wfin[w*64 + lane + 32] = whi;
    *(float4*)&vred[vpart*256 + 4*t63] = vac;
    if (lane == 0) svals[w] = s;
    __syncthreads();

    {   // att[t] = (attn@v + edge-weight @ We)/s
        int n = t >> 5;
        const float* wn = &wfin[n*64];
        float e0 = 0.f, e1 = 0.f;
        #pragma unroll
        for (int c = 0; c < 64; c += 2) {
            e0 = fmaf(wn[c],     We[c*DE + t],       e0);
            e1 = fmaf(wn[c + 1], We[(c + 1)*DE + t], e1);
        }
        float vsum = vred[t] + vred[256 + t] + vred[512 + t] + vred[768 + t];
        att[t] = (vsum + e0 + e1) / svals[n];
    }
    __syncthreads();

    {   // out = att@Wo + bo : 64 outputs x 4-way k-split
        int o = t63, kq = t >> 6;
        float a = 0.f;
        #pragma unroll
        for (int kk = 0; kk < 64; kk++) {
            int k = kq*64 + kk;
            a = fmaf(att[k], Wo[k*DO + o], a);
        }
        opart[kq*64 + o] = a;
    }
    __syncthreads();
    if (t < DO)
        out[i*DO + t] = bo[t] + opart[t] + opart[64 + t] + opart[128 + t] + opart[192 + t];
}

// ---------------------------------------------------------------------------
extern "C" void kernel_launch(void* const* d_in, const int* in_sizes, int n_in,
                              void* d_out, int out_size) {
    const float* x  = (const float*)d_in[0];
    const float* e  = (const float*)d_in[1];
    const float* Wq = (const float*)d_in[2];
    const float* Wk = (const float*)d_in[3];
    const float* Wv = (const float*)d_in[4];
    const float* We = (const float*)d_in[5];
    const float* Wo = (const float*)d_in[6];
    const float* bo = (const float*)d_in[7];
    float* out = (float*)d_out;

    proj_kernel<<<dim3(4, 8, 3), 256>>>(x, Wq, Wk, Wv);
    p_kernel<<<dim3(8, 8), 256>>>(We);
    qk_kernel<<<dim3(16, 16, 8), 256>>>();
    attn_kernel<<<512, 256>>>(e, We, Wo, bo, out);
}

// round 7
// speedup vs baseline: 2.2251x; 1.2619x over previous
#include <cuda_runtime.h>
#include <stdint.h>
#include <math.h>

#define L 512
#define DO 64      // D_ORIG
#define NH 8
#define DH 32
#define DE 256
#define SCALE 0.17677669529663687f  // 1/sqrt(32)

// Scratch (device globals — no allocations allowed)
__device__ float g_q[L*DE];
__device__ float g_k[L*DE];
__device__ float g_v[L*DE];
__device__ float g_p[L*512];            // [i][n*64+c], SCALE folded in
__device__ float g_sc[(size_t)NH*L*L];  // [n][i][j] base qk logits (SCALE folded)

#define CP_ASYNC16(sa, ga) asm volatile("cp.async.cg.shared.global [%0], [%1], 16;\n" :: "r"(sa), "l"(ga))
#define CP_COMMIT()        asm volatile("cp.async.commit_group;\n" ::: "memory")
#define CP_WAIT0()         asm volatile("cp.async.wait_group 0;\n" ::: "memory")

// ---------------------------------------------------------------------------
// Kernel 1: tiled GEMM  {q,k,v}[512x256] = x[512x64] @ W[64x256]
// ---------------------------------------------------------------------------
__global__ void proj_kernel(const float* __restrict__ x, const float* __restrict__ Wq,
                            const float* __restrict__ Wk, const float* __restrict__ Wv) {
    const float* W = (blockIdx.z == 0) ? Wq : (blockIdx.z == 1) ? Wk : Wv;
    float* outp    = (blockIdx.z == 0) ? g_q : (blockIdx.z == 1) ? g_k : g_v;
    int c0 = blockIdx.x * 64, i0 = blockIdx.y * 64;
    int t = threadIdx.x;
    __shared__ __align__(16) float xs[64][68];
    __shared__ __align__(16) float ws[64][68];
    for (int l = t; l < 1024; l += 256) {
        int r = l >> 4, c4 = (l & 15) * 4;
        *(float4*)&xs[r][c4] = *(const float4*)&x[(i0 + r)*DO + c4];
        *(float4*)&ws[r][c4] = *(const float4*)&W[r*DE + c0 + c4];
    }
    __syncthreads();
    int ty = t >> 4, tx = t & 15;
    float acc[4][4] = {};
    #pragma unroll
    for (int k = 0; k < 64; k++) {
        float4 b = *(const float4*)&ws[k][tx*4];
        float a0 = xs[ty*4+0][k], a1 = xs[ty*4+1][k], a2 = xs[ty*4+2][k], a3 = xs[ty*4+3][k];
        acc[0][0] = fmaf(a0, b.x, acc[0][0]); acc[0][1] = fmaf(a0, b.y, acc[0][1]);
        acc[0][2] = fmaf(a0, b.z, acc[0][2]); acc[0][3] = fmaf(a0, b.w, acc[0][3]);
        acc[1][0] = fmaf(a1, b.x, acc[1][0]); acc[1][1] = fmaf(a1, b.y, acc[1][1]);
        acc[1][2] = fmaf(a1, b.z, acc[1][2]); acc[1][3] = fmaf(a1, b.w, acc[1][3]);
        acc[2][0] = fmaf(a2, b.x, acc[2][0]); acc[2][1] = fmaf(a2, b.y, acc[2][1]);
        acc[2][2] = fmaf(a2, b.z, acc[2][2]); acc[2][3] = fmaf(a2, b.w, acc[2][3]);
        acc[3][0] = fmaf(a3, b.x, acc[3][0]); acc[3][1] = fmaf(a3, b.y, acc[3][1]);
        acc[3][2] = fmaf(a3, b.z, acc[3][2]); acc[3][3] = fmaf(a3, b.w, acc[3][3]);
    }
    #pragma unroll
    for (int m = 0; m < 4; m++)
        *(float4*)&outp[(i0 + ty*4 + m)*DE + c0 + tx*4] = *(float4*)&acc[m][0];
}

// ---------------------------------------------------------------------------
// Kernel 1b: p[i][n*64+c] = SCALE * sum_d q[i][n*32+d] * We[c][n*32+d]
// ---------------------------------------------------------------------------
__global__ void p_kernel(const float* __restrict__ We) {
    int i0 = blockIdx.x * 64, n = blockIdx.y;
    int t = threadIdx.x;
    __shared__ __align__(16) float qs[64][36];
    __shared__ __align__(16) float wes[32][68];
    for (int l = t; l < 512; l += 256) {
        int r = l >> 3, d4 = (l & 7) * 4;
        *(float4*)&qs[r][d4] = *(const float4*)&g_q[(i0 + r)*DE + n*DH + d4];
    }
    for (int l = t; l < 512; l += 256) {
        int c = l >> 3, d4 = (l & 7) * 4;
        float4 v4 = *(const float4*)&We[c*DE + n*DH + d4];
        wes[d4 + 0][c] = v4.x; wes[d4 + 1][c] = v4.y;
        wes[d4 + 2][c] = v4.z; wes[d4 + 3][c] = v4.w;
    }
    __syncthreads();
    int ty = t >> 4, tx = t & 15;
    float acc[4][4] = {};
    #pragma unroll
    for (int d = 0; d < 32; d++) {
        float4 b = *(const float4*)&wes[d][tx*4];
        float a0 = qs[ty*4+0][d], a1 = qs[ty*4+1][d], a2 = qs[ty*4+2][d], a3 = qs[ty*4+3][d];
        acc[0][0] = fmaf(a0, b.x, acc[0][0]); acc[0][1] = fmaf(a0, b.y, acc[0][1]);
        acc[0][2] = fmaf(a0, b.z, acc[0][2]); acc[0][3] = fmaf(a0, b.w, acc[0][3]);
        acc[1][0] = fmaf(a1, b.x, acc[1][0]); acc[1][1] = fmaf(a1, b.y, acc[1][1]);
        acc[1][2] = fmaf(a1, b.z, acc[1][2]); acc[1][3] = fmaf(a1, b.w, acc[1][3]);
        acc[2][0] = fmaf(a2, b.x, acc[2][0]); acc[2][1] = fmaf(a2, b.y, acc[2][1]);
        acc[2][2] = fmaf(a2, b.z, acc[2][2]); acc[2][3] = fmaf(a2, b.w, acc[2][3]);
        acc[3][0] = fmaf(a3, b.x, acc[3][0]); acc[3][1] = fmaf(a3, b.y, acc[3][1]);
        acc[3][2] = fmaf(a3, b.z, acc[3][2]); acc[3][3] = fmaf(a3, b.w, acc[3][3]);
    }
    #pragma unroll
    for (int m = 0; m < 4; m++) {
        #pragma unroll
        for (int j = 0; j < 4; j++) acc[m][j] *= SCALE;
        *(float4*)&g_p[(i0 + ty*4 + m)*512 + n*64 + tx*4] = *(float4*)&acc[m][0];
    }
}

// ---------------------------------------------------------------------------
// Kernel 2: base[n][i][j] = scale * q[i,nslice] . k[j,nslice]
// ---------------------------------------------------------------------------
__global__ void qk_kernel() {
    int n = blockIdx.z, i0 = blockIdx.y * 32, j0 = blockIdx.x * 32;
    int t = threadIdx.x;
    __shared__ float Qs[32][33], Ks[32][33];
    for (int l = t; l < 1024; l += 256) {
        int r = l >> 5, d = l & 31;
        Qs[r][d] = g_q[(i0 + r)*DE + n*DH + d];
        Ks[r][d] = g_k[(j0 + r)*DE + n*DH + d];
    }
    __syncthreads();
    int tx = t & 31, ty = t >> 5;
    float acc[4] = {0.f, 0.f, 0.f, 0.f};
    #pragma unroll
    for (int d = 0; d < 32; d++) {
        float kv = Ks[tx][d];
        #pragma unroll
        for (int m = 0; m < 4; m++) acc[m] = fmaf(Qs[ty*4 + m][d], kv, acc[m]);
    }
    #pragma unroll
    for (int m = 0; m < 4; m++)
        g_sc[((size_t)n*L + (i0 + ty*4 + m))*L + j0 + tx] = acc[m] * SCALE;
}

// ---------------------------------------------------------------------------
// Kernel 3 (hot): warp-autonomous fused attention. 1 CTA per query i.
// Warp w owns j-rows w*8..w*8+7 of every tile: loads them (cp.async),
// computes all-head scores (p broadcast), exp (no max needed: logits O(10)),
// edge-weight accum + attn@v for those rows. NO CTA barrier in the loop.
// Tail: cross-warp reductions + edge proj + @Wo + bo.
// ---------------------------------------------------------------------------
__global__ void __launch_bounds__(256, 4)
attn_kernel(const float* __restrict__ e, const float* __restrict__ We,
            const float* __restrict__ Wo, const float* __restrict__ bo,
            float* __restrict__ out) {
    int i = blockIdx.x, t = threadIdx.x;
    int w = t >> 5, lane = t & 31;
    int cq = lane >> 3, jg = lane & 7;    // phase-A mapping: quarter cq, row jg
    int jl = w*8 + jg;                    // local j row owned in phase A
    int vh = lane >> 3;                   // head of v-column 4*lane

    // espool: [2][64][68] e-tiles; tail arrays overlay it afterwards.
    __shared__ __align__(16) float espool[2*4352];
    __shared__ __align__(16) float ps[512];
    __shared__ __align__(16) float pes[64*8];      // [j_local][head]
    __shared__ float svals[NH];

    const float* ebase = e + (size_t)i*L*DO;

    // prologue: warp w prefetches ITS rows of tile 0 into buffer 0
    #pragma unroll
    for (int k2 = 0; k2 < 4; k2++) {
        int f = k2*32 + lane;             // float4 index in warp's 8x64 block
        int row = w*8 + (f >> 4), c4 = (f & 15) * 4;
        unsigned int sa = (unsigned int)__cvta_generic_to_shared(&espool[row*68 + c4]);
        CP_ASYNC16(sa, ebase + (size_t)row*64 + c4);
    }
    CP_COMMIT();

    ps[t]       = g_p[i*512 + t];
    ps[t + 256] = g_p[i*512 + t + 256];
    __syncthreads();    // ps visible to all warps (only CTA barrier before tail)

    float sacc0 = 0.f, sacc1 = 0.f;
    float wacc[16];
    #pragma unroll
    for (int n = 0; n < 16; n++) wacc[n] = 0.f;
    float4 va = make_float4(0.f,0.f,0.f,0.f), vb = make_float4(0.f,0.f,0.f,0.f);

    const float4* psf = (const float4*)ps;

    for (int tile = 0; tile < 8; tile++) {
        int b = tile & 1, j0 = tile * 64;
        CP_WAIT0();
        __syncwarp();     // prev phase-C reads of pes done before overwrite

        if (tile < 7) {   // prefetch own rows of next tile into other buffer
            #pragma unroll
            for (int k2 = 0; k2 < 4; k2++) {
                int f = k2*32 + lane;
                int row = w*8 + (f >> 4), c4 = (f & 15) * 4;
                unsigned int sa = (unsigned int)__cvta_generic_to_shared(
                    &espool[(b^1)*4352 + row*68 + c4]);
                CP_ASYNC16(sa, ebase + (size_t)(j0 + 64)*64 + (size_t)row*64 + c4);
            }
            CP_COMMIT();
        }

        // ---- Phase A: scores for row jl, ALL heads. Quarter cq of 64 cols.
        {
            const float4* er = (const float4*)&espool[b*4352 + jl*68];
            float4 ev0 = er[cq*4 + 0], ev1 = er[cq*4 + 1];
            float4 ev2 = er[cq*4 + 2], ev3 = er[cq*4 + 3];
            float acc[8];
            #pragma unroll
            for (int n = 0; n < 8; n++) {
                const float4* pq = psf + n*16 + cq*4;
                float4 p0 = pq[0], p1 = pq[1], p2 = pq[2], p3 = pq[3];
                float a = 0.f;
                a = fmaf(ev0.x, p0.x, a); a = fmaf(ev0.y, p0.y, a);
                a = fmaf(ev0.z, p0.z, a); a = fmaf(ev0.w, p0.w, a);
                a = fmaf(ev1.x, p1.x, a); a = fmaf(ev1.y, p1.y, a);
                a = fmaf(ev1.z, p1.z, a); a = fmaf(ev1.w, p1.w, a);
                a = fmaf(ev2.x, p2.x, a); a = fmaf(ev2.y, p2.y, a);
                a = fmaf(ev2.z, p2.z, a); a = fmaf(ev2.w, p2.w, a);
                a = fmaf(ev3.x, p3.x, a); a = fmaf(ev3.y, p3.y, a);
                a = fmaf(ev3.z, p3.z, a); a = fmaf(ev3.w, p3.w, a);
                acc[n] = a;
            }
            #pragma unroll
            for (int off = 8; off <= 16; off <<= 1)
                #pragma unroll
                for (int n = 0; n < 8; n++)
                    acc[n] += __shfl_xor_sync(0xffffffffu, acc[n], off);
            // this lane finalizes heads 2cq, 2cq+1 for j = j0 + jl
            int j = j0 + jl;
            float b0 = g_sc[((size_t)(2*cq)*L + i)*L + j];
            float b1 = g_sc[((size_t)(2*cq + 1)*L + i)*L + j];
            float pe0 = __expf(acc[2*cq] + b0);
            float pe1 = __expf(acc[2*cq + 1] + b1);
            sacc0 += pe0; sacc1 += pe1;
            *(float2*)&pes[jl*8 + 2*cq] = make_float2(pe0, pe1);
        }
        __syncwarp();     // pes rows of this warp visible warp-wide

        // ---- Phase C: edge-weights + attn@v over OWN 8 rows
        #pragma unroll
        for (int q = 0; q < 8; q++) {
            int jj = w*8 + q;
            const float* prow = &pes[jj*8];
            float2 p01 = *(const float2*)&prow[0];
            float2 p23 = *(const float2*)&prow[2];
            float2 p45 = *(const float2*)&prow[4];
            float2 p67 = *(const float2*)&prow[6];
            float2 ee = *(const float2*)&espool[b*4352 + jj*68 + 2*lane];
            wacc[0]  = fmaf(p01.x, ee.x, wacc[0]);  wacc[1]  = fmaf(p01.x, ee.y, wacc[1]);
            wacc[2]  = fmaf(p01.y, ee.x, wacc[2]);  wacc[3]  = fmaf(p01.y, ee.y, wacc[3]);
            wacc[4]  = fmaf(p23.x, ee.x, wacc[4]);  wacc[5]  = fmaf(p23.x, ee.y, wacc[5]);
            wacc[6]  = fmaf(p23.y, ee.x, wacc[6]);  wacc[7]  = fmaf(p23.y, ee.y, wacc[7]);
            wacc[8]  = fmaf(p45.x, ee.x, wacc[8]);  wacc[9]  = fmaf(p45.x, ee.y, wacc[9]);
            wacc[10] = fmaf(p45.y, ee.x, wacc[10]); wacc[11] = fmaf(p45.y, ee.y, wacc[11]);
            wacc[12] = fmaf(p67.x, ee.x, wacc[12]); wacc[13] = fmaf(p67.x, ee.y, wacc[13]);
            wacc[14] = fmaf(p67.y, ee.x, wacc[14]); wacc[15] = fmaf(p67.y, ee.y, wacc[15]);
            // attn@v: cols 4*lane (head vh) and 128+4*lane (head vh+4)
            const float4* vv = (const float4*)&g_v[(size_t)(j0 + jj)*DE];
            float4 v0 = vv[lane];
            float4 v1 = vv[lane + 32];
            float pva = prow[vh];
            float pvb = prow[4 + vh];
            va.x = fmaf(pva, v0.x, va.x); va.y = fmaf(pva, v0.y, va.y);
            va.z = fmaf(pva, v0.z, va.z); va.w = fmaf(pva, v0.w, va.w);
            vb.x = fmaf(pvb, v1.x, vb.x); vb.y = fmaf(pvb, v1.y, vb.y);
            vb.z = fmaf(pvb, v1.z, vb.z); vb.w = fmaf(pvb, v1.w, vb.w);
        }
    }

    // ---------------- Tail: cross-warp reductions + projections
    __syncthreads();
    float* wpart = espool;            // [8 warps][8 heads][64 c] = 4096 floats
    float* vred  = espool + 4352;     // [8 warps][256]           = 2048
    float* stmp  = espool + 6400;     // [8 heads][64]            = 512
    float* att   = espool + 6912;     // [256]
    float* opart = espool + 7168;     // [4][64]                  = 256
    float* wfin  = espool + 7424;     // [8 heads][64]            = 512

    #pragma unroll
    for (int n = 0; n < 8; n++)
        *(float2*)&wpart[(w*8 + n)*64 + 2*lane] = make_float2(wacc[2*n], wacc[2*n + 1]);
    *(float4*)&vred[w*256 + 4*lane]       = va;
    *(float4*)&vred[w*256 + 128 + 4*lane] = vb;
    stmp[(2*cq)*64 + jl]     = sacc0;
    stmp[(2*cq + 1)*64 + jl] = sacc1;
    __syncthreads();

    {   // softmax denominators: warp n reduces head n
        float sv = stmp[w*64 + lane] + stmp[w*64 + lane + 32];
        #pragma unroll
        for (int off = 16; off; off >>= 1) sv += __shfl_xor_sync(0xffffffffu, sv, off);
        if (lane == 0) svals[w] = sv;
    }
    {   // wfin[n][c] = sum over warps; thread t covers (t>>6, t&63) and (+4, t&63)
        int n0 = t >> 6, c0 = t & 63;
        float f0 = 0.f, f1 = 0.f;
        #pragma unroll
        for (int sw = 0; sw < 8; sw++) {
            f0 += wpart[(sw*8 + n0)*64 + c0];
            f1 += wpart[(sw*8 + n0 + 4)*64 + c0];
        }
        wfin[n0*64 + c0] = f0; wfin[(n0 + 4)*64 + c0] = f1;
    }
    __syncthreads();

    {   // att[t] = (attn@v + edge-weight @ We)/s
        int n = t >> 5;
        const float* wn = &wfin[n*64];
        float e0 = 0.f, e1 = 0.f;
        #pragma unroll
        for (int c = 0; c < 64; c += 2) {
            e0 = fmaf(wn[c],     We[c*DE + t],       e0);
            e1 = fmaf(wn[c + 1], We[(c + 1)*DE + t], e1);
        }
        float vsum = 0.f;
        #pragma unroll
        for (int sw = 0; sw < 8; sw++) vsum += vred[sw*256 + t];
        att[t] = (vsum + e0 + e1) / svals[n];
    }
    __syncthreads();

    {   // out = att@Wo + bo : 64 outputs x 4-way k-split
        int o = t & 63, kq = t >> 6;
        float a = 0.f;
        #pragma unroll
        for (int kk = 0; kk < 64; kk++) {
            int k = kq*64 + kk;
            a = fmaf(att[k], Wo[k*DO + o], a);
        }
        opart[kq*64 + o] = a;
    }
    __syncthreads();
    if (t < DO)
        out[i*DO + t] = bo[t] + opart[t] + opart[64 + t] + opart[128 + t] + opart[192 + t];
}

// ---------------------------------------------------------------------------
extern "C" void kernel_launch(void* const* d_in, const int* in_sizes, int n_in,
                              void* d_out, int out_size) {
    const float* x  = (const float*)d_in[0];
    const float* e  = (const float*)d_in[1];
    const float* Wq = (const float*)d_in[2];
    const float* Wk = (const float*)d_in[3];
    const float* Wv = (const float*)d_in[4];
    const float* We = (const float*)d_in[5];
    const float* Wo = (const float*)d_in[6];
    const float* bo = (const float*)d_in[7];
    float* out = (float*)d_out;

    proj_kernel<<<dim3(4, 8, 3), 256>>>(x, Wq, Wk, Wv);
    p_kernel<<<dim3(8, 8), 256>>>(We);
    qk_kernel<<<dim3(16, 16, 8), 256>>>();
    attn_kernel<<<512, 256>>>(e, We, Wo, bo, out);
}

// round 8
// speedup vs baseline: 2.3718x; 1.0659x over previous
#include <cuda_runtime.h>
#include <stdint.h>
#include <math.h>

#define L 512
#define DO 64      // D_ORIG
#define NH 8
#define DH 32
#define DE 256
#define SCALE 0.17677669529663687f  // 1/sqrt(32)

// Scratch (device globals — no allocations allowed)
__device__ float g_q[L*DE];
__device__ float g_k[L*DE];
__device__ float g_v[L*DE];
__device__ float g_p[L*512];            // [i][n*64+c], SCALE folded in
__device__ float g_sc[(size_t)NH*L*L];  // [n][i][j] base qk logits (SCALE folded)

#define CP_ASYNC16(sa, ga) asm volatile("cp.async.cg.shared.global [%0], [%1], 16;\n" :: "r"(sa), "l"(ga))
#define CP_COMMIT()        asm volatile("cp.async.commit_group;\n" ::: "memory")
#define CP_WAIT0()         asm volatile("cp.async.wait_group 0;\n" ::: "memory")

// ---- f32x2 packed helpers (sm_10x) --------------------------------------
__device__ __forceinline__ void lds2(unsigned long long &a, unsigned long long &b, unsigned sa) {
    asm volatile("ld.shared.v2.u64 {%0,%1}, [%2];" : "=l"(a), "=l"(b) : "r"(sa));
}
__device__ __forceinline__ unsigned long long ffma2(unsigned long long a, unsigned long long b,
                                                    unsigned long long c) {
    unsigned long long d;
    asm("fma.rn.f32x2 %0, %1, %2, %3;" : "=l"(d) : "l"(a), "l"(b), "l"(c));
    return d;
}
__device__ __forceinline__ unsigned long long pack2(float x, float y) {
    unsigned long long r;
    asm("mov.b64 %0, {%1, %2};" : "=l"(r) : "f"(x), "f"(y));
    return r;
}
__device__ __forceinline__ void unpack2(unsigned long long v, float &x, float &y) {
    asm("mov.b64 {%0, %1}, %2;" : "=f"(x), "=f"(y) : "l"(v));
}

// ---------------------------------------------------------------------------
// Kernel 1: tiled GEMM  {q,k,v}[512x256] = x[512x64] @ W[64x256]
// ---------------------------------------------------------------------------
__global__ void proj_kernel(const float* __restrict__ x, const float* __restrict__ Wq,
                            const float* __restrict__ Wk, const float* __restrict__ Wv) {
    const float* W = (blockIdx.z == 0) ? Wq : (blockIdx.z == 1) ? Wk : Wv;
    float* outp    = (blockIdx.z == 0) ? g_q : (blockIdx.z == 1) ? g_k : g_v;
    int c0 = blockIdx.x * 64, i0 = blockIdx.y * 64;
    int t = threadIdx.x;
    __shared__ __align__(16) float xs[64][68];
    __shared__ __align__(16) float ws[64][68];
    for (int l = t; l < 1024; l += 256) {
        int r = l >> 4, c4 = (l & 15) * 4;
        *(float4*)&xs[r][c4] = *(const float4*)&x[(i0 + r)*DO + c4];
        *(float4*)&ws[r][c4] = *(const float4*)&W[r*DE + c0 + c4];
    }
    __syncthreads();
    int ty = t >> 4, tx = t & 15;
    float acc[4][4] = {};
    #pragma unroll
    for (int k = 0; k < 64; k++) {
        float4 b = *(const float4*)&ws[k][tx*4];
        float a0 = xs[ty*4+0][k], a1 = xs[ty*4+1][k], a2 = xs[ty*4+2][k], a3 = xs[ty*4+3][k];
        acc[0][0] = fmaf(a0, b.x, acc[0][0]); acc[0][1] = fmaf(a0, b.y, acc[0][1]);
        acc[0][2] = fmaf(a0, b.z, acc[0][2]); acc[0][3] = fmaf(a0, b.w, acc[0][3]);
        acc[1][0] = fmaf(a1, b.x, acc[1][0]); acc[1][1] = fmaf(a1, b.y, acc[1][1]);
        acc[1][2] = fmaf(a1, b.z, acc[1][2]); acc[1][3] = fmaf(a1, b.w, acc[1][3]);
        acc[2][0] = fmaf(a2, b.x, acc[2][0]); acc[2][1] = fmaf(a2, b.y, acc[2][1]);
        acc[2][2] = fmaf(a2, b.z, acc[2][2]); acc[2][3] = fmaf(a2, b.w, acc[2][3]);
        acc[3][0] = fmaf(a3, b.x, acc[3][0]); acc[3][1] = fmaf(a3, b.y, acc[3][1]);
        acc[3][2] = fmaf(a3, b.z, acc[3][2]); acc[3][3] = fmaf(a3, b.w, acc[3][3]);
    }
    #pragma unroll
    for (int m = 0; m < 4; m++)
        *(float4*)&outp[(i0 + ty*4 + m)*DE + c0 + tx*4] = *(float4*)&acc[m][0];
}

// ---------------------------------------------------------------------------
// Kernel 1b: p[i][n*64+c] = SCALE * sum_d q[i][n*32+d] * We[c][n*32+d]
// ---------------------------------------------------------------------------
__global__ void p_kernel(const float* __restrict__ We) {
    int i0 = blockIdx.x * 64, n = blockIdx.y;
    int t = threadIdx.x;
    __shared__ __align__(16) float qs[64][36];
    __shared__ __align__(16) float wes[32][68];
    for (int l = t; l < 512; l += 256) {
        int r = l >> 3, d4 = (l & 7) * 4;
        *(float4*)&qs[r][d4] = *(const float4*)&g_q[(i0 + r)*DE + n*DH + d4];
    }
    for (int l = t; l < 512; l += 256) {
        int c = l >> 3, d4 = (l & 7) * 4;
        float4 v4 = *(const float4*)&We[c*DE + n*DH + d4];
        wes[d4 + 0][c] = v4.x; wes[d4 + 1][c] = v4.y;
        wes[d4 + 2][c] = v4.z; wes[d4 + 3][c] = v4.w;
    }
    __syncthreads();
    int ty = t >> 4, tx = t & 15;
    float acc[4][4] = {};
    #pragma unroll
    for (int d = 0; d < 32; d++) {
        float4 b = *(const float4*)&wes[d][tx*4];
        float a0 = qs[ty*4+0][d], a1 = qs[ty*4+1][d], a2 = qs[ty*4+2][d], a3 = qs[ty*4+3][d];
        acc[0][0] = fmaf(a0, b.x, acc[0][0]); acc[0][1] = fmaf(a0, b.y, acc[0][1]);
        acc[0][2] = fmaf(a0, b.z, acc[0][2]); acc[0][3] = fmaf(a0, b.w, acc[0][3]);
        acc[1][0] = fmaf(a1, b.x, acc[1][0]); acc[1][1] = fmaf(a1, b.y, acc[1][1]);
        acc[1][2] = fmaf(a1, b.z, acc[1][2]); acc[1][3] = fmaf(a1, b.w, acc[1][3]);
        acc[2][0] = fmaf(a2, b.x, acc[2][0]); acc[2][1] = fmaf(a2, b.y, acc[2][1]);
        acc[2][2] = fmaf(a2, b.z, acc[2][2]); acc[2][3] = fmaf(a2, b.w, acc[2][3]);
        acc[3][0] = fmaf(a3, b.x, acc[3][0]); acc[3][1] = fmaf(a3, b.y, acc[3][1]);
        acc[3][2] = fmaf(a3, b.z, acc[3][2]); acc[3][3] = fmaf(a3, b.w, acc[3][3]);
    }
    #pragma unroll
    for (int m = 0; m < 4; m++) {
        #pragma unroll
        for (int j = 0; j < 4; j++) acc[m][j] *= SCALE;
        *(float4*)&g_p[(i0 + ty*4 + m)*512 + n*64 + tx*4] = *(float4*)&acc[m][0];
    }
}

// ---------------------------------------------------------------------------
// Kernel 2: base[n][i][j] = scale * q[i,nslice] . k[j,nslice]
// ---------------------------------------------------------------------------
__global__ void qk_kernel() {
    int n = blockIdx.z, i0 = blockIdx.y * 32, j0 = blockIdx.x * 32;
    int t = threadIdx.x;
    __shared__ float Qs[32][33], Ks[32][33];
    for (int l = t; l < 1024; l += 256) {
        int r = l >> 5, d = l & 31;
        Qs[r][d] = g_q[(i0 + r)*DE + n*DH + d];
        Ks[r][d] = g_k[(j0 + r)*DE + n*DH + d];
    }
    __syncthreads();
    int tx = t & 31, ty = t >> 5;
    float acc[4] = {0.f, 0.f, 0.f, 0.f};
    #pragma unroll
    for (int d = 0; d < 32; d++) {
        float kv = Ks[tx][d];
        #pragma unroll
        for (int m = 0; m < 4; m++) acc[m] = fmaf(Qs[ty*4 + m][d], kv, acc[m]);
    }
    #pragma unroll
    for (int m = 0; m < 4; m++)
        g_sc[((size_t)n*L + (i0 + ty*4 + m))*L + j0 + tx] = acc[m] * SCALE;
}

// ---------------------------------------------------------------------------
// Kernel 3 (hot): warp-autonomous fused attention, f32x2 math.
// Warp w owns j-rows w*8..w*8+7 of every tile. No CTA barrier in the loop.
// ---------------------------------------------------------------------------
__global__ void __launch_bounds__(256, 3)
attn_kernel(const float* __restrict__ e, const float* __restrict__ We,
            const float* __restrict__ Wo, const float* __restrict__ bo,
            float* __restrict__ out) {
    int i = blockIdx.x, t = threadIdx.x;
    int w = t >> 5, lane = t & 31;
    int cq = lane >> 3, jg = lane & 7;    // phase-A mapping: quarter cq, row jg
    int jl = w*8 + jg;                    // local j row owned in phase A
    int vh = lane >> 3;                   // head of v-column 4*lane

    __shared__ __align__(16) float espool[2*4352];   // [2][64][68]
    __shared__ __align__(16) float ps[512];
    __shared__ __align__(16) float pes[64*8];        // [j_local][head]
    __shared__ __align__(16) float pes_t[8*64];      // [head][j_local]
    __shared__ float svals[NH];

    const float* ebase = e + (size_t)i*L*DO;
    unsigned es_sa  = (unsigned)__cvta_generic_to_shared(espool);
    unsigned ps_sa  = (unsigned)__cvta_generic_to_shared(ps);
    unsigned pes_sa = (unsigned)__cvta_generic_to_shared(pes);

    // prologue: warp w prefetches ITS rows of tile 0 into buffer 0
    #pragma unroll
    for (int k2 = 0; k2 < 4; k2++) {
        int f = k2*32 + lane;
        int row = w*8 + (f >> 4), c4 = (f & 15) * 4;
        CP_ASYNC16(es_sa + (unsigned)(row*68 + c4)*4, ebase + (size_t)row*64 + c4);
    }
    CP_COMMIT();

    ps[t]       = g_p[i*512 + t];
    ps[t + 256] = g_p[i*512 + t + 256];
    __syncthreads();    // ps visible to all warps

    float sacc0 = 0.f, sacc1 = 0.f;
    unsigned long long wx[4] = {0ULL,0ULL,0ULL,0ULL};  // (head 2n, head 2n+1) col x
    unsigned long long wy[4] = {0ULL,0ULL,0ULL,0ULL};  // same, col y
    float4 va = make_float4(0.f,0.f,0.f,0.f), vb = make_float4(0.f,0.f,0.f,0.f);

    for (int tile = 0; tile < 8; tile++) {
        int b = tile & 1, j0 = tile * 64;
        CP_WAIT0();
        __syncwarp();     // prev phase-C reads of pes done before overwrite

        if (tile < 7) {   // prefetch own rows of next tile into other buffer
            #pragma unroll
            for (int k2 = 0; k2 < 4; k2++) {
                int f = k2*32 + lane;
                int row = w*8 + (f >> 4), c4 = (f & 15) * 4;
                CP_ASYNC16(es_sa + (unsigned)((b^1)*4352 + row*68 + c4)*4,
                           ebase + (size_t)(j0 + 64)*64 + (size_t)row*64 + c4);
            }
            CP_COMMIT();
        }

        // ---- Phase A: scores for row jl, ALL heads (f32x2 dot, quarter cq)
        {
            unsigned erow = es_sa + (unsigned)(b*4352 + jl*68 + cq*16)*4;
            unsigned long long e0,e1,e2,e3,e4,e5,e6,e7;
            lds2(e0,e1, erow);      lds2(e2,e3, erow + 16);
            lds2(e4,e5, erow + 32); lds2(e6,e7, erow + 48);
            float accs[8];
            #pragma unroll
            for (int n = 0; n < 8; n++) {
                unsigned psa = ps_sa + (unsigned)(n*64 + cq*16)*4;
                unsigned long long p0,p1,p2,p3,p4,p5,p6,p7;
                lds2(p0,p1, psa);      lds2(p2,p3, psa + 16);
                lds2(p4,p5, psa + 32); lds2(p6,p7, psa + 48);
                unsigned long long a = ffma2(e0, p0, 0ULL);
                a = ffma2(e1, p1, a); a = ffma2(e2, p2, a); a = ffma2(e3, p3, a);
                a = ffma2(e4, p4, a); a = ffma2(e5, p5, a); a = ffma2(e6, p6, a);
                a = ffma2(e7, p7, a);
                float x, y; unpack2(a, x, y);
                accs[n] = x + y;
            }
            #pragma unroll
            for (int off = 8; off <= 16; off <<= 1)
                #pragma unroll
                for (int n = 0; n < 8; n++)
                    accs[n] += __shfl_xor_sync(0xffffffffu, accs[n], off);
            // this lane finalizes heads 2cq, 2cq+1 for j = j0 + jl
            int j = j0 + jl;
            float b0 = g_sc[((size_t)(2*cq)*L + i)*L + j];
            float b1 = g_sc[((size_t)(2*cq + 1)*L + i)*L + j];
            float pe0 = __expf(accs[2*cq] + b0);
            float pe1 = __expf(accs[2*cq + 1] + b1);
            sacc0 += pe0; sacc1 += pe1;
            *(float2*)&pes[jl*8 + 2*cq] = make_float2(pe0, pe1);
            pes_t[(2*cq)*64 + jl]     = pe0;
            pes_t[(2*cq + 1)*64 + jl] = pe1;
        }
        __syncwarp();     // pes rows of this warp visible warp-wide

        // ---- Phase C: edge-weights (f32x2) + attn@v over OWN 8 rows
        float2 pa2 = make_float2(0.f,0.f), pb2 = make_float2(0.f,0.f);
        #pragma unroll
        for (int q = 0; q < 8; q++) {
            int jj = w*8 + q;
            unsigned long long p01, p23, p45, p67;
            unsigned prow = pes_sa + (unsigned)(jj*32);
            lds2(p01, p23, prow); lds2(p45, p67, prow + 16);
            float2 ee = *(const float2*)&espool[b*4352 + jj*68 + 2*lane];
            unsigned long long xx = pack2(ee.x, ee.x);
            unsigned long long yy = pack2(ee.y, ee.y);
            wx[0] = ffma2(p01, xx, wx[0]); wy[0] = ffma2(p01, yy, wy[0]);
            wx[1] = ffma2(p23, xx, wx[1]); wy[1] = ffma2(p23, yy, wy[1]);
            wx[2] = ffma2(p45, xx, wx[2]); wy[2] = ffma2(p45, yy, wy[2]);
            wx[3] = ffma2(p67, xx, wx[3]); wy[3] = ffma2(p67, yy, wy[3]);
            // attn@v: pe scalars via transposed layout, broadcast LDS.64 per 2q
            if ((q & 1) == 0) {
                pa2 = *(const float2*)&pes_t[vh*64 + jj];
                pb2 = *(const float2*)&pes_t[(vh + 4)*64 + jj];
            }
            float pva = (q & 1) ? pa2.y : pa2.x;
            float pvb = (q & 1) ? pb2.y : pb2.x;
            const float4* vv = (const float4*)&g_v[(size_t)(j0 + jj)*DE];
            float4 v0 = vv[lane];
            float4 v1 = vv[lane + 32];
            va.x = fmaf(pva, v0.x, va.x); va.y = fmaf(pva, v0.y, va.y);
            va.z = fmaf(pva, v0.z, va.z); va.w = fmaf(pva, v0.w, va.w);
            vb.x = fmaf(pvb, v1.x, vb.x); vb.y = fmaf(pvb, v1.y, vb.y);
            vb.z = fmaf(pvb, v1.z, vb.z); vb.w = fmaf(pvb, v1.w, vb.w);
        }
    }

    // ---------------- Tail: cross-warp reductions + projections
    __syncthreads();
    float* wpart = espool;            // [8 warps][8 heads][64 c] = 4096 floats
    float* vred  = espool + 4352;     // [8 warps][256]           = 2048
    float* stmp  = espool + 6400;     // [8 heads][64]            = 512
    float* att   = espool + 6912;     // [256]
    float* opart = espool + 7168;     // [4][64]                  = 256
    float* wfin  = espool + 7424;     // [8 heads][64]            = 512

    #pragma unroll
    for (int np = 0; np < 4; np++) {
        float x0, x1, y0, y1;
        unpack2(wx[np], x0, x1);
        unpack2(wy[np], y0, y1);
        *(float2*)&wpart[(w*8 + 2*np)*64 + 2*lane]     = make_float2(x0, y0);
        *(float2*)&wpart[(w*8 + 2*np + 1)*64 + 2*lane] = make_float2(x1, y1);
    }
    *(float4*)&vred[w*256 + 4*lane]       = va;
    *(float4*)&vred[w*256 + 128 + 4*lane] = vb;
    stmp[(2*cq)*64 + jl]     = sacc0;
    stmp[(2*cq + 1)*64 + jl] = sacc1;
    __syncthreads();

    {   // softmax denominators: warp n reduces head n
        float sv = stmp[w*64 + lane] + stmp[w*64 + lane + 32];
        #pragma unroll
        for (int off = 16; off; off >>= 1) sv += __shfl_xor_sync(0xffffffffu, sv, off);
        if (lane == 0) svals[w] = sv;
    }
    {   // wfin[n][c] = sum over warps
        int n0 = t >> 6, c0 = t & 63;
        float f0 = 0.f, f1 = 0.f;
        #pragma unroll
        for (int sw = 0; sw < 8; sw++) {
            f0 += wpart[(sw*8 + n0)*64 + c0];
            f1 += wpart[(sw*8 + n0 + 4)*64 + c0];
        }
        wfin[n0*64 + c0] = f0; wfin[(n0 + 4)*64 + c0] = f1;
    }
    __syncthreads();

    {   // att[t] = (attn@v + edge-weight @ We)/s
        int n = t >> 5;
        const float* wn = &wfin[n*64];
        float e0 = 0.f, e1 = 0.f;
        #pragma unroll
        for (int c = 0; c < 64; c += 2) {
            e0 = fmaf(wn[c],     We[c*DE + t],       e0);
            e1 = fmaf(wn[c + 1], We[(c + 1)*DE + t], e1);
        }
        float vsum = 0.f;
        #pragma unroll
        for (int sw = 0; sw < 8; sw++) vsum += vred[sw*256 + t];
        att[t] = (vsum + e0 + e1) / svals[n];
    }
    __syncthreads();

    {   // out = att@Wo + bo : 64 outputs x 4-way k-split
        int o = t & 63, kq = t >> 6;
        float a = 0.f;
        #pragma unroll
        for (int kk = 0; kk < 64; kk++) {
            int k = kq*64 + kk;
            a = fmaf(att[k], Wo[k*DO + o], a);
        }
        opart[kq*64 + o] = a;
    }
    __syncthreads();
    if (t < DO)
        out[i*DO + t] = bo[t] + opart[t] + opart[64 + t] + opart[128 + t] + opart[192 + t];
}

// ---------------------------------------------------------------------------
extern "C" void kernel_launch(void* const* d_in, const int* in_sizes, int n_in,
                              void* d_out, int out_size) {
    const float* x  = (const float*)d_in[0];
    const float* e  = (const float*)d_in[1];
    const float* Wq = (const float*)d_in[2];
    const float* Wk = (const float*)d_in[3];
    const float* Wv = (const float*)d_in[4];
    const float* We = (const float*)d_in[5];
    const float* Wo = (const float*)d_in[6];
    const float* bo = (const float*)d_in[7];
    float* out = (float*)d_out;

    proj_kernel<<<dim3(4, 8, 3), 256>>>(x, Wq, Wk, Wv);
    p_kernel<<<dim3(8, 8), 256>>>(We);
    qk_kernel<<<dim3(16, 16, 8), 256>>>();
    attn_kernel<<<512, 256>>>(e, We, Wo, bo, out);
}